// round 13
// baseline (speedup 1.0000x reference)
#include <cuda_runtime.h>
#include <cstdint>

#define B_   4096
#define XD   128
#define YD   64
#define T_   200
#define LAT  100
#define CH   50
#define NBK  296
#define NT   512
#define KP   232
#define NP   416
#define NKT  29
#define AS2  244     // A row stride in float2 units (mod 16 == 4 -> conflict-free frags)
#define GST  424

// SMEM floats, per block: 18444 = 73776 B (x2/SM = 147.5 KB)
#define OFF_BIH 0          // [300] folded (r,z: bih+bhh; n: bih)
#define OFF_BHH 300        // [300]
#define OFF_BL1 600
#define OFF_BL2 700
#define OFF_H   764        // [100][20] fp32 h ([j][r])
#define OFF_A   2764       // float2 [16][AS2]: (hi,lo); cols 0-127 x_il, 128-227 h
#define OFF_YP  10572      // [64][17]
#define OFF_GX  11660      // [16][GST] mma output
#define OFF_O1  OFF_GX     // [100][20] overlay (barrier-separated)
#define SMEM_FLOATS 18444

__device__ float2 g_WB[KP * NP];   // fused B, (hi,lo) tf32 planes

__device__ __forceinline__ float tf32_(float v) {
    unsigned r; asm("cvt.rna.tf32.f32 %0, %1;" : "=r"(r) : "f"(v));
    return __uint_as_float(r);
}
__device__ __forceinline__ float2 tfsplit(float v) {
    const float h = tf32_(v);
    return make_float2(h, tf32_(v - h));
}
__device__ __forceinline__ void mma8(float d[4], float a0, float a1, float a2, float a3,
                                     float b0, float b1) {
    asm("mma.sync.aligned.m16n8k8.row.col.f32.tf32.tf32.f32 "
        "{%0,%1,%2,%3}, {%4,%5,%6,%7}, {%8,%9}, {%0,%1,%2,%3};"
        : "+f"(d[0]), "+f"(d[1]), "+f"(d[2]), "+f"(d[3])
        : "r"(__float_as_uint(a0)), "r"(__float_as_uint(a1)),
          "r"(__float_as_uint(a2)), "r"(__float_as_uint(a3)),
          "r"(__float_as_uint(b0)), "r"(__float_as_uint(b1)));
}
__device__ __forceinline__ float rcp_(float x) {
    float r; asm("rcp.approx.f32 %0, %1;" : "=f"(r) : "f"(x)); return r;
}
__device__ __forceinline__ void rcp4(const float d[4], float inv[4]) {
    const float p1 = d[0] * d[1], p2 = p1 * d[2], p3 = p2 * d[3];
    const float q3 = rcp_(p3);
    inv[3] = q3 * p2;
    const float q2 = q3 * d[3];
    inv[2] = q2 * p1;
    const float q1 = q2 * d[2];
    inv[1] = q1 * d[0];
    inv[0] = q1 * d[1];
}
__device__ __forceinline__ float fsig(float x) {
    return __fdividef(1.0f, 1.0f + __expf(-x));
}
__device__ __forceinline__ float ftanh_(float x) {
    float e = __expf(2.0f * x);
    return 1.0f - __fdividef(2.0f, e + 1.0f);
}

// ---- prep: bake Wih|Whh into zero-padded fused tf32 (hi,lo) B [KP x NP] ----
__global__ void prep_kernel(const float* __restrict__ Wih, const float* __restrict__ Whh)
{
    for (int i = blockIdx.x * blockDim.x + threadIdx.x; i < KP * NP;
         i += gridDim.x * blockDim.x) {
        const int k = i / NP, n = i % NP;
        float v = 0.f;
        if (n < 200) {                       // r|z gates: x then h along K
            if (k < XD) v = Wih[k * 300 + n];
            else if (k < 228) v = Whh[(k - XD) * 300 + n];
        } else if (n < 300) {                // n-gate x part
            if (k < XD) v = Wih[k * 300 + n];
        } else if (n >= 304 && n < 404) {    // n-gate h part (Whh col 200+(n-304))
            if (k >= XD && k < 228) v = Whh[(k - XD) * 300 + (n - 104)];
        }
        g_WB[i] = tfsplit(v);
    }
}

extern "C" __global__ void __launch_bounds__(NT, 2) gru_kernel(
    const float* __restrict__ x, const float* __restrict__ y, const void* __restrict__ ymask,
    const float* __restrict__ Wmu1, const float* __restrict__ bmu1,
    const float* __restrict__ Wmu2, const float* __restrict__ bmu2,
    const float* __restrict__ bih, const float* __restrict__ bhh,
    const float* __restrict__ Wl1, const float* __restrict__ bl1,
    const float* __restrict__ Wl2, const float* __restrict__ bl2,
    const float* __restrict__ Wc1, const float* __restrict__ bc1,
    const float* __restrict__ Wc2, const float* __restrict__ bc2,
    float* __restrict__ out, int has_cls)
{
    extern __shared__ float sm[];
    float2* Af = (float2*)(sm + OFF_A);
    const int tid  = threadIdx.x;
    const int lane = tid & 31;
    const int wid  = tid >> 5;        // 0..15
    const int g    = lane >> 2;       // mma group 0..7
    const int cc   = lane & 3;        // thread-in-group
    const int b0   = (B_ * blockIdx.x) / NBK;
    const int nr   = (B_ * (blockIdx.x + 1)) / NBK - b0;   // 13 or 14
    const int j0   = lane * 4;

    // ---- stage biases; zero YP and A pad cols 228-231 ----
    for (int i = tid; i < 300; i += NT) {
        sm[OFF_BIH + i] = (i < 200) ? bih[i] + bhh[i] : bih[i];
        sm[OFF_BHH + i] = bhh[i];
    }
    for (int i = tid; i < LAT; i += NT) sm[OFF_BL1 + i] = bl1[i];
    for (int i = tid; i < YD;  i += NT) sm[OFF_BL2 + i] = bl2[i];
    for (int i = tid; i < YD * 17; i += NT) sm[OFF_YP + i] = 0.f;
    if (tid < 64) Af[(tid >> 2) * AS2 + 228 + (tid & 3)] = make_float2(0.f, 0.f);

    // ---- mask dtype detection (uint8 / int32 / float32), deterministic ----
    const unsigned word = ((const unsigned*)ymask)[tid];
    const int big = __syncthreads_or((word & 0xFEFEFEFEu) != 0u);
    const int odd = __syncthreads_or((word & 0xFFFFFF00u) != 0u);
    const int mode = big ? 2 : (odd ? 0 : 1);

    // ---- stage x (fp32) into GX scratch [16][132] ----
    float* Xs = sm + OFF_GX;
    for (int i = tid; i < 16 * XD; i += NT) {
        const int r = i & 15, k = i >> 4;
        Xs[r * 132 + k] = (r < nr) ? __ldg(&x[(size_t)(b0 + r) * XD + k]) : 0.f;
    }
    __syncthreads();

    // ---- h0 encoder (FFMA, once): warp = row ----
    float* tmp = sm + OFF_GX + 2112;   // [100][20] scratch
    if (lane < 25) {
        float a[4] = {0, 0, 0, 0};
        for (int k = 0; k < XD; k++) {
            const float xv = Xs[wid * 132 + k];
            const float4 w = __ldg((const float4*)&Wmu1[k * LAT + j0]);
            a[0] = fmaf(xv, w.x, a[0]); a[1] = fmaf(xv, w.y, a[1]);
            a[2] = fmaf(xv, w.z, a[2]); a[3] = fmaf(xv, w.w, a[3]);
        }
        const float4 bb = __ldg((const float4*)&bmu1[j0]);
        tmp[(j0 + 0) * 20 + wid] = ftanh_(a[0] + bb.x);
        tmp[(j0 + 1) * 20 + wid] = ftanh_(a[1] + bb.y);
        tmp[(j0 + 2) * 20 + wid] = ftanh_(a[2] + bb.z);
        tmp[(j0 + 3) * 20 + wid] = ftanh_(a[3] + bb.w);
    }
    __syncthreads();
    if (lane < 25) {
        float a[4] = {0, 0, 0, 0};
        for (int k = 0; k < LAT; k++) {
            const float tv = tmp[k * 20 + wid];
            const float4 w = __ldg((const float4*)&Wmu2[k * LAT + j0]);
            a[0] = fmaf(tv, w.x, a[0]); a[1] = fmaf(tv, w.y, a[1]);
            a[2] = fmaf(tv, w.z, a[2]); a[3] = fmaf(tv, w.w, a[3]);
        }
        const float4 bb = __ldg((const float4*)&bmu2[j0]);
        const float hv[4] = {a[0] + bb.x, a[1] + bb.y, a[2] + bb.z, a[3] + bb.w};
#pragma unroll
        for (int i = 0; i < 4; i++) {
            sm[OFF_H + (j0 + i) * 20 + wid] = hv[i];
            Af[wid * AS2 + 128 + j0 + i] = tfsplit(hv[i]);
        }
    }

    // ---- y/mask preload (1024 = 16r x 64d, 2/thread) ----
    float yv[2], mfv[2];
    auto preload = [&](int t) {
#pragma unroll
        for (int i = 0; i < 2; i++) {
            const int e = tid + NT * i;
            const int r = e & 15, d = e >> 4;
            if (r < nr) {
                const size_t off = (size_t)(b0 + r) * (YD * T_) + (size_t)d * T_ + t;
                yv[i] = __ldg(&y[off]);
                float m;
                if (mode == 0)      m = (((const unsigned char*)ymask)[off] != 0) ? 1.f : 0.f;
                else if (mode == 1) m = (((const int*)ymask)[off] != 0) ? 1.f : 0.f;
                else                m = (((const float*)ymask)[off] != 0.f) ? 1.f : 0.f;
                mfv[i] = m;
            } else { yv[i] = 0.f; mfv[i] = 0.f; }
        }
    };
    preload(0);
    __syncthreads();

    // this warp's n-tiles (52 tiles of 8 cols over 16 warps)
    const int tset[4] = {wid, wid + 16, wid + 32, (wid < 4) ? 48 + wid : -1};

    // ================= main recurrence (5 barriers/step) =================
    for (int t = 0; t < T_; ++t) {
        // -- teacher forcing -> A cols 0..127 (value,mask interleaved, tf32 split) --
#pragma unroll
        for (int i = 0; i < 2; i++) {
            const int e = tid + NT * i;
            const int r = e & 15, d = e >> 4;
            const float m  = mfv[i];
            const float yp = sm[OFF_YP + d * 17 + r];
            const float yin = (m != 0.f) ? yv[i] : yp;
            Af[r * AS2 + 2 * d]     = tfsplit(yin);
            Af[r * AS2 + 2 * d + 1] = make_float2(m, 0.f);
        }
        if (t + 1 < T_) preload(t + 1);
        __syncthreads();

        // -- P1 (tensor): GX[16x404] = A[16x232] @ WB[232x416], 3xTF32 --
        {
            float D[4][4];
#pragma unroll
            for (int q = 0; q < 4; q++)
#pragma unroll
                for (int i = 0; i < 4; i++) D[q][i] = 0.f;

            for (int kt = 0; kt < NKT; kt++) {
                const int kk = kt * 8;
                const float2 f00 = Af[g * AS2 + kk + cc];
                const float2 f10 = Af[(g + 8) * AS2 + kk + cc];
                const float2 f01 = Af[g * AS2 + kk + cc + 4];
                const float2 f11 = Af[(g + 8) * AS2 + kk + cc + 4];
#pragma unroll
                for (int q = 0; q < 4; q++) {
                    const int n0t = tset[q] * 8;
                    if (tset[q] < 0) continue;
                    if (n0t >= 200 && ((n0t < 304) ? (kt >= 16) : (kt < 16))) continue;
                    const float2 b0 = __ldg(&g_WB[(kk + cc) * NP + n0t + g]);
                    const float2 b1 = __ldg(&g_WB[(kk + cc + 4) * NP + n0t + g]);
                    mma8(D[q], f00.x, f10.x, f01.x, f11.x, b0.x, b1.x);
                    mma8(D[q], f00.x, f10.x, f01.x, f11.x, b0.y, b1.y);
                    mma8(D[q], f00.y, f10.y, f01.y, f11.y, b0.x, b1.x);
                }
            }
#pragma unroll
            for (int q = 0; q < 4; q++) {
                if (tset[q] < 0) continue;
                const int n0t = tset[q] * 8;
                *(float2*)&sm[OFF_GX + g * GST + n0t + 2 * cc] =
                    make_float2(D[q][0], D[q][1]);
                *(float2*)&sm[OFF_GX + (g + 8) * GST + n0t + 2 * cc] =
                    make_float2(D[q][2], D[q][3]);
            }
        }
        __syncthreads();

        // -- gates (batched-RCP): h = (1-z)*n + z*h; write H + A h-part split --
        if (tid < 400) {
            const int j  = tid % 100;
            const int r0 = (tid / 100) << 2;
            float gr[4], gz[4], gxv[4], gh[4];
#pragma unroll
            for (int i = 0; i < 4; i++) {
                const float* GX = sm + OFF_GX + (r0 + i) * GST;
                gr[i]  = GX[j]       + sm[OFF_BIH + j];
                gz[i]  = GX[100 + j] + sm[OFF_BIH + 100 + j];
                gxv[i] = GX[200 + j] + sm[OFF_BIH + 200 + j];
                gh[i]  = GX[304 + j] + sm[OFF_BHH + 200 + j];
            }
            float dr[4], dz[4], rg[4], zg[4];
#pragma unroll
            for (int i = 0; i < 4; i++) {
                dr[i] = 1.f + __expf(-fminf(fmaxf(gr[i], -15.f), 15.f));
                dz[i] = 1.f + __expf(-fminf(fmaxf(gz[i], -15.f), 15.f));
            }
            rcp4(dr, rg);
            rcp4(dz, zg);
            float dn[4], iv[4];
#pragma unroll
            for (int i = 0; i < 4; i++) {
                float u = gxv[i] + rg[i] * gh[i];
                u = fminf(fmaxf(u, -10.f), 10.f);
                dn[i] = __expf(2.f * u) + 1.f;
            }
            rcp4(dn, iv);
            const float4 hvv = *(const float4*)&sm[OFF_H + j * 20 + r0];
            const float ho[4] = {hvv.x, hvv.y, hvv.z, hvv.w};
            float hn[4];
#pragma unroll
            for (int i = 0; i < 4; i++) {
                const float n = 1.f - 2.f * iv[i];
                hn[i] = (1.f - zg[i]) * n + zg[i] * ho[i];
                Af[(r0 + i) * AS2 + 128 + j] = tfsplit(hn[i]);
            }
            *(float4*)&sm[OFF_H + j * 20 + r0] = make_float4(hn[0], hn[1], hn[2], hn[3]);
        }
        __syncthreads();

        // -- G3 (FFMA): o1 = tanh(h @ Wl1 + bl1) --
        if (lane < 25) {
            const int r3 = (wid & 3) << 2;
            const int jc = (wid >> 2) * 25 + lane;
            float a0 = 0.f, a1 = 0.f, a2 = 0.f, a3 = 0.f;
#pragma unroll 4
            for (int k = 0; k < LAT; k++) {
                const float4 a = *(const float4*)&sm[OFF_H + k * 20 + r3];
                const float w = __ldg(&Wl1[k * LAT + jc]);
                a0 = fmaf(a.x, w, a0); a1 = fmaf(a.y, w, a1);
                a2 = fmaf(a.z, w, a2); a3 = fmaf(a.w, w, a3);
            }
            const float bb = sm[OFF_BL1 + jc];
            float d[4], iv[4];
            const float v[4] = {a0 + bb, a1 + bb, a2 + bb, a3 + bb};
#pragma unroll
            for (int i = 0; i < 4; i++) {
                const float u = fminf(fmaxf(v[i], -10.f), 10.f);
                d[i] = __expf(2.f * u) + 1.f;
            }
            rcp4(d, iv);
            sm[OFF_O1 + jc * 20 + r3 + 0] = 1.f - 2.f * iv[0];
            sm[OFF_O1 + jc * 20 + r3 + 1] = 1.f - 2.f * iv[1];
            sm[OFF_O1 + jc * 20 + r3 + 2] = 1.f - 2.f * iv[2];
            sm[OFF_O1 + jc * 20 + r3 + 3] = 1.f - 2.f * iv[3];
        }
        __syncthreads();

        // -- G4 (FFMA): out_t = o1 @ Wl2 + bl2; write out + YP --
        {
            const int row = lane & 15;
            const int jc  = (wid << 2) + ((lane >> 4) << 1);
            float a0 = 0.f, a1 = 0.f;
#pragma unroll 4
            for (int k = 0; k < LAT; k++) {
                const float a = sm[OFF_O1 + k * 20 + row];
                const float2 wv = __ldg((const float2*)&Wl2[k * YD + jc]);
                a0 = fmaf(a, wv.x, a0); a1 = fmaf(a, wv.y, a1);
            }
            const float v0 = a0 + sm[OFF_BL2 + jc];
            const float v1 = a1 + sm[OFF_BL2 + jc + 1];
            if (row < nr) {
                float* op = out + (size_t)(b0 + row) * (YD * T_) + (size_t)jc * T_ + t;
                op[0]  = v0;
                op[T_] = v1;
            }
            sm[OFF_YP + jc * 17 + row]       = v0;
            sm[OFF_YP + (jc + 1) * 17 + row] = v1;
        }
        __syncthreads();
    }

    // ---- classifier: sigmoid(relu(h_T @ Wc1 + bc1) @ Wc2 + bc2) ----
    if (has_cls) {
        float* scr = sm + OFF_GX + 2112;
        for (int idx = tid; idx < 16 * CH; idx += NT) {
            const int r = idx & 15, c = idx >> 4;
            float acc = __ldg(&bc1[c]);
            for (int k = 0; k < LAT; k++)
                acc = fmaf(sm[OFF_H + k * 20 + r], __ldg(&Wc1[k * CH + c]), acc);
            scr[c * 16 + r] = fmaxf(acc, 0.f);
        }
        __syncthreads();
        if (tid < nr) {
            float acc = __ldg(&bc2[0]);
            for (int c = 0; c < CH; c++)
                acc = fmaf(scr[c * 16 + tid], __ldg(&Wc2[c]), acc);
            out[(size_t)B_ * YD * T_ + b0 + tid] = fsig(acc);
        }
    }
}

extern "C" void kernel_launch(void* const* d_in, const int* in_sizes, int n_in,
                              void* d_out, int out_size)
{
    cudaFuncSetAttribute(gru_kernel, cudaFuncAttributeMaxDynamicSharedMemorySize,
                         SMEM_FLOATS * (int)sizeof(float));
    prep_kernel<<<128, 256>>>((const float*)d_in[11], (const float*)d_in[13]);
    const int has_cls = (out_size > B_ * YD * T_) ? 1 : 0;
    gru_kernel<<<NBK, NT, SMEM_FLOATS * sizeof(float)>>>(
        (const float*)d_in[0],   // x
        (const float*)d_in[1],   // y
        d_in[2],                 // y_mask (dtype auto-detected)
        (const float*)d_in[3],  (const float*)d_in[4],   // Wmu1, bmu1
        (const float*)d_in[5],  (const float*)d_in[6],   // Wmu2, bmu2
        (const float*)d_in[12], (const float*)d_in[14],  // bih, bhh
        (const float*)d_in[15], (const float*)d_in[16],  // Wl1, bl1
        (const float*)d_in[17], (const float*)d_in[18],  // Wl2, bl2
        (const float*)d_in[19], (const float*)d_in[20],  // Wc1, bc1
        (const float*)d_in[21], (const float*)d_in[22],  // Wc2, bc2
        (float*)d_out, has_cls);
}

// round 14
// speedup vs baseline: 1.6624x; 1.6624x over previous
#include <cuda_runtime.h>
#include <cstdint>

#define B_   4096
#define XD   128
#define YD   64
#define T_   200
#define LAT  100
#define CH   50
#define NBK  148
#define NT   512
#define KP   232
#define NP   416
#define NKT  29
#define AS2  244     // A row stride (float2); conflict-free per half-warp phase
#define GST  426     // GX row stride (fp32); conflict-free f2 stores
#define O1S  108     // O1 row stride (float2)

// SMEM floats: 35724 = 142896 B (1 block/SM)
#define OFF_BIH 0          // [300] folded (r,z: bih+bhh; n: bih)
#define OFF_BHH 300        // [300]
#define OFF_BL1 600
#define OFF_BL2 700
#define OFF_H   764        // [100][36] fp32 h ([j][r])
#define OFF_A   4364       // float2 [32][AS2]: cols 0-127 x_il, 128-227 h, 228-231 pad
#define OFF_YP  19980      // [64][33]
#define OFF_GX  22092      // [32][GST] fp32; O1 float2 [32][O1S] overlays (barrier-sep)
#define SMEM_FLOATS 35724

__device__ float2 g_WB[KP * NP];     // fused big B (hi,lo)
__device__ float2 g_W1[104 * 104];   // Wl1 padded
__device__ float2 g_W2[104 * 64];    // Wl2 padded

__device__ __forceinline__ float tf32_(float v) {
    unsigned r; asm("cvt.rna.tf32.f32 %0, %1;" : "=r"(r) : "f"(v));
    return __uint_as_float(r);
}
__device__ __forceinline__ float2 tfsplit(float v) {
    const float h = tf32_(v);
    return make_float2(h, tf32_(v - h));
}
__device__ __forceinline__ void mma8(float d[4], float a0, float a1, float a2, float a3,
                                     float b0, float b1) {
    asm("mma.sync.aligned.m16n8k8.row.col.f32.tf32.tf32.f32 "
        "{%0,%1,%2,%3}, {%4,%5,%6,%7}, {%8,%9}, {%0,%1,%2,%3};"
        : "+f"(d[0]), "+f"(d[1]), "+f"(d[2]), "+f"(d[3])
        : "r"(__float_as_uint(a0)), "r"(__float_as_uint(a1)),
          "r"(__float_as_uint(a2)), "r"(__float_as_uint(a3)),
          "r"(__float_as_uint(b0)), "r"(__float_as_uint(b1)));
}
// 3xTF32 pass set for one m16 row-tile
__device__ __forceinline__ void mma3(float d[4], const float2 F[4], float2 b0, float2 b1) {
    mma8(d, F[0].x, F[1].x, F[2].x, F[3].x, b0.x, b1.x);
    mma8(d, F[0].x, F[1].x, F[2].x, F[3].x, b0.y, b1.y);
    mma8(d, F[0].y, F[1].y, F[2].y, F[3].y, b0.x, b1.x);
}
// load 8 A-fragments (rows g,g+8,g+16,g+24 x cols col,col+4)
__device__ __forceinline__ void ldfrag(float2 F[8], const float2* base, int st, int g, int col) {
    F[0] = base[g * st + col];        F[1] = base[(g + 8) * st + col];
    F[2] = base[g * st + col + 4];    F[3] = base[(g + 8) * st + col + 4];
    F[4] = base[(g + 16) * st + col]; F[5] = base[(g + 24) * st + col];
    F[6] = base[(g + 16) * st + col + 4]; F[7] = base[(g + 24) * st + col + 4];
}
__device__ __forceinline__ float rcp_(float x) {
    float r; asm("rcp.approx.f32 %0, %1;" : "=f"(r) : "f"(x)); return r;
}
__device__ __forceinline__ void rcp4(const float d[4], float inv[4]) {
    const float p1 = d[0] * d[1], p2 = p1 * d[2], p3 = p2 * d[3];
    const float q3 = rcp_(p3);
    inv[3] = q3 * p2;
    const float q2 = q3 * d[3];
    inv[2] = q2 * p1;
    const float q1 = q2 * d[2];
    inv[1] = q1 * d[0];
    inv[0] = q1 * d[1];
}
__device__ __forceinline__ float fsig(float x) {
    return __fdividef(1.0f, 1.0f + __expf(-x));
}
__device__ __forceinline__ float ftanh_(float x) {
    float e = __expf(2.0f * x);
    return 1.0f - __fdividef(2.0f, e + 1.0f);
}

// ---- prep: bake all tensor-side weights into zero-padded tf32 (hi,lo) planes ----
__global__ void prep_kernel(const float* __restrict__ Wih, const float* __restrict__ Whh,
                            const float* __restrict__ Wl1, const float* __restrict__ Wl2)
{
    const int total = KP * NP + 104 * 104 + 104 * 64;
    for (int i = blockIdx.x * blockDim.x + threadIdx.x; i < total;
         i += gridDim.x * blockDim.x) {
        float v = 0.f;
        if (i < KP * NP) {
            const int k = i / NP, n = i % NP;
            if (n < 200) {                     // r|z: x (k<128) then h (128<=k<228)
                if (k < XD) v = Wih[k * 300 + n];
                else if (k < 228) v = Whh[(k - XD) * 300 + n];
            } else if (n < 300) {              // n-gate x part
                if (k < XD) v = Wih[k * 300 + n];
            } else if (n >= 304 && n < 404) {  // n-gate h part
                if (k >= XD && k < 228) v = Whh[(k - XD) * 300 + (n - 104)];
            }
            g_WB[i] = tfsplit(v);
        } else if (i < KP * NP + 104 * 104) {
            const int e = i - KP * NP, k = e / 104, n = e % 104;
            if (k < 100 && n < 100) v = Wl1[k * 100 + n];
            g_W1[e] = tfsplit(v);
        } else {
            const int e = i - KP * NP - 104 * 104, k = e / 64, n = e % 64;
            if (k < 100) v = Wl2[k * 64 + n];
            g_W2[e] = tfsplit(v);
        }
    }
}

extern "C" __global__ void __launch_bounds__(NT, 1) gru_kernel(
    const float* __restrict__ x, const float* __restrict__ y, const void* __restrict__ ymask,
    const float* __restrict__ Wmu1, const float* __restrict__ bmu1,
    const float* __restrict__ Wmu2, const float* __restrict__ bmu2,
    const float* __restrict__ bih, const float* __restrict__ bhh,
    const float* __restrict__ bl1, const float* __restrict__ bl2,
    const float* __restrict__ Wc1, const float* __restrict__ bc1,
    const float* __restrict__ Wc2, const float* __restrict__ bc2,
    float* __restrict__ out, int has_cls)
{
    extern __shared__ float sm[];
    float2* Af  = (float2*)(sm + OFF_A);
    float2* O1f = (float2*)(sm + OFF_GX);   // overlays GX (barrier-separated)
    const int tid  = threadIdx.x;
    const int lane = tid & 31;
    const int wid  = tid >> 5;        // 0..15
    const int g    = lane >> 2;       // mma group 0..7
    const int cc   = lane & 3;
    const int b0   = (B_ * blockIdx.x) / NBK;
    const int nr   = (B_ * (blockIdx.x + 1)) / NBK - b0;   // 27 or 28
    const int j0   = lane * 4;

    // ---- stage biases; zero YP + A pad cols 228-231 ----
    for (int i = tid; i < 300; i += NT) {
        sm[OFF_BIH + i] = (i < 200) ? bih[i] + bhh[i] : bih[i];
        sm[OFF_BHH + i] = bhh[i];
    }
    for (int i = tid; i < LAT; i += NT) sm[OFF_BL1 + i] = bl1[i];
    for (int i = tid; i < YD;  i += NT) sm[OFF_BL2 + i] = bl2[i];
    for (int i = tid; i < YD * 33; i += NT) sm[OFF_YP + i] = 0.f;
    if (tid < 128) Af[(tid >> 2) * AS2 + 228 + (tid & 3)] = make_float2(0.f, 0.f);

    // ---- mask dtype detection (uint8 / int32 / float32), deterministic ----
    const unsigned word = ((const unsigned*)ymask)[tid];
    const int big = __syncthreads_or((word & 0xFEFEFEFEu) != 0u);
    const int odd = __syncthreads_or((word & 0xFFFFFF00u) != 0u);
    const int mode = big ? 2 : (odd ? 0 : 1);

    // ---- stage x fp32 into GX scratch [32][132] ----
    float* Xs = sm + OFF_GX;
    for (int i = tid; i < 32 * XD; i += NT) {
        const int r = i & 31, k = i >> 5;
        Xs[r * 132 + k] = (r < nr) ? __ldg(&x[(size_t)(b0 + r) * XD + k]) : 0.f;
    }
    __syncthreads();

    // ---- h0 encoder (FFMA, once): warp = 2 rows ----
    float* tmp = sm + OFF_GX + 4224;   // [100][36]
    {
        const int r0 = 2 * wid, r1 = r0 + 1;
        if (lane < 25) {
            float a[8] = {0,0,0,0,0,0,0,0};
            for (int k = 0; k < XD; k++) {
                const float x0 = Xs[r0 * 132 + k], x1 = Xs[r1 * 132 + k];
                const float4 w = __ldg((const float4*)&Wmu1[k * LAT + j0]);
                a[0] = fmaf(x0, w.x, a[0]); a[1] = fmaf(x0, w.y, a[1]);
                a[2] = fmaf(x0, w.z, a[2]); a[3] = fmaf(x0, w.w, a[3]);
                a[4] = fmaf(x1, w.x, a[4]); a[5] = fmaf(x1, w.y, a[5]);
                a[6] = fmaf(x1, w.z, a[6]); a[7] = fmaf(x1, w.w, a[7]);
            }
            const float4 bb = __ldg((const float4*)&bmu1[j0]);
            const float bc[4] = {bb.x, bb.y, bb.z, bb.w};
#pragma unroll
            for (int i = 0; i < 4; i++) {
                tmp[(j0 + i) * 36 + r0] = ftanh_(a[i] + bc[i]);
                tmp[(j0 + i) * 36 + r1] = ftanh_(a[4 + i] + bc[i]);
            }
        }
        __syncthreads();
        if (lane < 25) {
            float a[8] = {0,0,0,0,0,0,0,0};
            for (int k = 0; k < LAT; k++) {
                const float x0 = tmp[k * 36 + r0], x1 = tmp[k * 36 + r1];
                const float4 w = __ldg((const float4*)&Wmu2[k * LAT + j0]);
                a[0] = fmaf(x0, w.x, a[0]); a[1] = fmaf(x0, w.y, a[1]);
                a[2] = fmaf(x0, w.z, a[2]); a[3] = fmaf(x0, w.w, a[3]);
                a[4] = fmaf(x1, w.x, a[4]); a[5] = fmaf(x1, w.y, a[5]);
                a[6] = fmaf(x1, w.z, a[6]); a[7] = fmaf(x1, w.w, a[7]);
            }
            const float4 bb = __ldg((const float4*)&bmu2[j0]);
            const float bc[4] = {bb.x, bb.y, bb.z, bb.w};
#pragma unroll
            for (int i = 0; i < 4; i++) {
                const float h0a = a[i] + bc[i], h0b = a[4 + i] + bc[i];
                sm[OFF_H + (j0 + i) * 36 + r0] = h0a;
                sm[OFF_H + (j0 + i) * 36 + r1] = h0b;
                Af[r0 * AS2 + 128 + j0 + i] = tfsplit(h0a);
                Af[r1 * AS2 + 128 + j0 + i] = tfsplit(h0b);
            }
        }
    }

    // ---- y/mask preload (2048 = 32r x 64d, 4/thread) ----
    float yv[4], mfv[4];
    auto preload = [&](int t) {
#pragma unroll
        for (int i = 0; i < 4; i++) {
            const int e = tid + NT * i;
            const int r = e & 31, d = e >> 5;
            if (r < nr) {
                const size_t off = (size_t)(b0 + r) * (YD * T_) + (size_t)d * T_ + t;
                yv[i] = __ldg(&y[off]);
                float m;
                if (mode == 0)      m = (((const unsigned char*)ymask)[off] != 0) ? 1.f : 0.f;
                else if (mode == 1) m = (((const int*)ymask)[off] != 0) ? 1.f : 0.f;
                else                m = (((const float*)ymask)[off] != 0.f) ? 1.f : 0.f;
                mfv[i] = m;
            } else { yv[i] = 0.f; mfv[i] = 0.f; }
        }
    };
    preload(0);
    __syncthreads();

    const int tset[4] = {wid, wid + 16, wid + 32, (wid < 4) ? 48 + wid : -1};

    // ================= main recurrence (5 barriers/step) =================
    for (int t = 0; t < T_; ++t) {
        // -- teacher forcing -> A cols 0..127 --
#pragma unroll
        for (int i = 0; i < 4; i++) {
            const int e = tid + NT * i;
            const int r = e & 31, d = e >> 5;
            const float m  = mfv[i];
            const float yp = sm[OFF_YP + d * 33 + r];
            const float yin = (m != 0.f) ? yv[i] : yp;
            Af[r * AS2 + 2 * d]     = tfsplit(yin);
            Af[r * AS2 + 2 * d + 1] = make_float2(m, 0.f);
        }
        if (t + 1 < T_) preload(t + 1);
        __syncthreads();

        // -- P1 (tensor): GX[32x~408] = A[32x232] @ WB, 3xTF32, M=32 --
        {
            float D[4][8];
#pragma unroll
            for (int q = 0; q < 4; q++)
#pragma unroll
                for (int i = 0; i < 8; i++) D[q][i] = 0.f;
            for (int kt = 0; kt < NKT; kt++) {
                const int kk = kt * 8;
                float2 F[8];
                ldfrag(F, Af, AS2, g, kk + cc);
#pragma unroll
                for (int q = 0; q < 4; q++) {
                    const int tl = tset[q];
                    if (tl < 0) continue;
                    const int n0t = tl * 8;
                    if (n0t >= 200 && ((n0t < 304) ? (kt >= 16) : (kt < 16))) continue;
                    const float2 b0v = __ldg(&g_WB[(kk + cc) * NP + n0t + g]);
                    const float2 b1v = __ldg(&g_WB[(kk + cc + 4) * NP + n0t + g]);
                    mma3(&D[q][0], F,     b0v, b1v);
                    mma3(&D[q][4], F + 4, b0v, b1v);
                }
            }
#pragma unroll
            for (int q = 0; q < 4; q++) {
                if (tset[q] < 0) continue;
                const int n0t = tset[q] * 8;
#pragma unroll
                for (int i = 0; i < 8; i += 2) {
                    const int row = g + (i >> 2) * 16 + ((i >> 1) & 1) * 8;
                    *(float2*)&sm[OFF_GX + row * GST + n0t + 2 * cc] =
                        make_float2(D[q][i], D[q][i + 1]);
                }
            }
        }
        __syncthreads();

        // -- gates (batched RCP): h = (1-z)*n + z*h; writes H + A h-split --
#pragma unroll
        for (int it = 0; it < 2; ++it) {
            const int idx = tid + NT * it;     // 800 = 100j x 8 row-quads
            if (idx < 800) {
                const int j  = idx % 100;
                const int r0 = (idx / 100) << 2;
                float gr[4], gz[4], gxv[4], gh[4];
#pragma unroll
                for (int i = 0; i < 4; i++) {
                    const float* GX = sm + OFF_GX + (r0 + i) * GST;
                    gr[i]  = GX[j]       + sm[OFF_BIH + j];
                    gz[i]  = GX[100 + j] + sm[OFF_BIH + 100 + j];
                    gxv[i] = GX[200 + j] + sm[OFF_BIH + 200 + j];
                    gh[i]  = GX[304 + j] + sm[OFF_BHH + 200 + j];
                }
                float dr[4], dz[4], rg[4], zg[4];
#pragma unroll
                for (int i = 0; i < 4; i++) {
                    dr[i] = 1.f + __expf(-fminf(fmaxf(gr[i], -15.f), 15.f));
                    dz[i] = 1.f + __expf(-fminf(fmaxf(gz[i], -15.f), 15.f));
                }
                rcp4(dr, rg);
                rcp4(dz, zg);
                float dn[4], iv[4];
#pragma unroll
                for (int i = 0; i < 4; i++) {
                    float u = gxv[i] + rg[i] * gh[i];
                    u = fminf(fmaxf(u, -10.f), 10.f);
                    dn[i] = __expf(2.f * u) + 1.f;
                }
                rcp4(dn, iv);
#pragma unroll
                for (int i = 0; i < 4; i++) {
                    const float n  = 1.f - 2.f * iv[i];
                    const float ho = sm[OFF_H + j * 36 + r0 + i];
                    const float hn = (1.f - zg[i]) * n + zg[i] * ho;
                    sm[OFF_H + j * 36 + r0 + i] = hn;
                    Af[(r0 + i) * AS2 + 128 + j] = tfsplit(hn);
                }
            }
        }
        __syncthreads();

        // -- G3 (tensor): o1 = tanh(h @ Wl1 + bl1) -> O1f (overlays GX) --
        if (wid < 13) {
            const int n0 = wid * 8;
            float D[8];
#pragma unroll
            for (int i = 0; i < 8; i++) D[i] = 0.f;
            for (int kt = 0; kt < 13; kt++) {
                const int kk = kt * 8;
                float2 F[8];
                ldfrag(F, Af, AS2, g, 128 + kk + cc);
                const float2 b0v = __ldg(&g_W1[(kk + cc) * 104 + n0 + g]);
                const float2 b1v = __ldg(&g_W1[(kk + cc + 4) * 104 + n0 + g]);
                mma3(&D[0], F, b0v, b1v);
                mma3(&D[4], F + 4, b0v, b1v);
            }
            float dv[8], iv[8];
#pragma unroll
            for (int i = 0; i < 8; i++) {
                const int col = n0 + 2 * cc + (i & 1);
                const float bb = (col < 100) ? sm[OFF_BL1 + col] : 0.f;
                const float u = fminf(fmaxf(D[i] + bb, -10.f), 10.f);
                dv[i] = __expf(2.f * u) + 1.f;
            }
            rcp4(dv, iv);
            rcp4(dv + 4, iv + 4);
#pragma unroll
            for (int i = 0; i < 8; i++) {
                const int row = g + (i >> 2) * 16 + ((i >> 1) & 1) * 8;
                const int col = n0 + 2 * cc + (i & 1);
                O1f[row * O1S + col] = tfsplit(1.f - 2.f * iv[i]);
            }
        }
        __syncthreads();

        // -- G4 (tensor): out_t = o1 @ Wl2 + bl2; writes out + YP --
        if (wid < 8) {
            const int n0 = wid * 8;
            float D[8];
#pragma unroll
            for (int i = 0; i < 8; i++) D[i] = 0.f;
            for (int kt = 0; kt < 13; kt++) {
                const int kk = kt * 8;
                float2 F[8];
                ldfrag(F, O1f, O1S, g, kk + cc);
                const float2 b0v = __ldg(&g_W2[(kk + cc) * 64 + n0 + g]);
                const float2 b1v = __ldg(&g_W2[(kk + cc + 4) * 64 + n0 + g]);
                mma3(&D[0], F, b0v, b1v);
                mma3(&D[4], F + 4, b0v, b1v);
            }
#pragma unroll
            for (int i = 0; i < 8; i++) {
                const int row = g + (i >> 2) * 16 + ((i >> 1) & 1) * 8;
                const int col = n0 + 2 * cc + (i & 1);
                const float v = D[i] + sm[OFF_BL2 + col];
                if (row < nr)
                    out[(size_t)(b0 + row) * (YD * T_) + (size_t)col * T_ + t] = v;
                sm[OFF_YP + col * 33 + row] = v;
            }
        }
        __syncthreads();
    }

    // ---- classifier: sigmoid(relu(h_T @ Wc1 + bc1) @ Wc2 + bc2) ----
    if (has_cls) {
        float* scr = sm + OFF_GX;
        for (int idx = tid; idx < 32 * CH; idx += NT) {
            const int r = idx & 31, c = idx >> 5;
            float acc = __ldg(&bc1[c]);
            for (int k = 0; k < LAT; k++)
                acc = fmaf(sm[OFF_H + k * 36 + r], __ldg(&Wc1[k * CH + c]), acc);
            scr[c * 36 + r] = fmaxf(acc, 0.f);
        }
        __syncthreads();
        if (tid < nr) {
            float acc = __ldg(&bc2[0]);
            for (int c = 0; c < CH; c++)
                acc = fmaf(scr[c * 36 + tid], __ldg(&Wc2[c]), acc);
            out[(size_t)B_ * YD * T_ + b0 + tid] = fsig(acc);
        }
    }
}

extern "C" void kernel_launch(void* const* d_in, const int* in_sizes, int n_in,
                              void* d_out, int out_size)
{
    cudaFuncSetAttribute(gru_kernel, cudaFuncAttributeMaxDynamicSharedMemorySize,
                         SMEM_FLOATS * (int)sizeof(float));
    prep_kernel<<<128, 256>>>((const float*)d_in[11], (const float*)d_in[13],
                              (const float*)d_in[15], (const float*)d_in[17]);
    const int has_cls = (out_size > B_ * YD * T_) ? 1 : 0;
    gru_kernel<<<NBK, NT, SMEM_FLOATS * sizeof(float)>>>(
        (const float*)d_in[0],   // x
        (const float*)d_in[1],   // y
        d_in[2],                 // y_mask (dtype auto-detected)
        (const float*)d_in[3],  (const float*)d_in[4],   // Wmu1, bmu1
        (const float*)d_in[5],  (const float*)d_in[6],   // Wmu2, bmu2
        (const float*)d_in[12], (const float*)d_in[14],  // bih, bhh
        (const float*)d_in[16], (const float*)d_in[18],  // bl1, bl2
        (const float*)d_in[19], (const float*)d_in[20],  // Wc1, bc1
        (const float*)d_in[21], (const float*)d_in[22],  // Wc2, bc2
        (float*)d_out, has_cls);
}

// round 15
// speedup vs baseline: 1.7026x; 1.0242x over previous
#include <cuda_runtime.h>
#include <cstdint>

#define B_   4096
#define XD   128
#define YD   64
#define T_   200
#define LAT  100
#define CH   50
#define NBK  148
#define NT   1024
#define KP   232
#define NP   416
#define NKT  29
#define AS2  244     // A row stride (float2)
#define GST  426     // GX row stride (fp32)
#define O1S  108     // O1 row stride (float2)

// SMEM floats: 35724 = 142896 B (1 block/SM)
#define OFF_BIH 0
#define OFF_BHH 300
#define OFF_BL1 600
#define OFF_BL2 700
#define OFF_H   764        // [100][36] fp32 h ([j][r])
#define OFF_A   4364       // float2 [32][AS2]
#define OFF_YP  19980      // [64][33]
#define OFF_GX  22092      // [32][GST]; O1 float2 [32][O1S] overlays
#define SMEM_FLOATS 35724

__device__ float2 g_WB[KP * NP];
__device__ float2 g_W1[104 * 104];
__device__ float2 g_W2[104 * 64];

// 52 n-tiles cost-balanced over 32 warps (H=29kt, M=16kt, L=13kt; max 48 units)
__device__ const short TSET[32][3] = {
 {0,-1,-1},{1,-1,-1},{2,-1,-1},{3,-1,-1},{4,-1,-1},{5,-1,-1},{6,-1,-1},{7,-1,-1},
 {8,-1,-1},{9,-1,-1},{10,-1,-1},{11,-1,-1},{12,-1,-1},{13,-1,-1},{14,-1,-1},{15,-1,-1},
 {16,-1,-1},{17,-1,-1},{18,-1,-1},
 {19,38,-1},{20,39,-1},{21,40,-1},{22,41,-1},{23,42,-1},{24,43,-1},
 {25,26,27},{28,29,30},{31,32,33},{34,35,36},{37,44,45},{46,47,48},{49,50,51}};

__device__ __forceinline__ float tf32_(float v) {
    unsigned r; asm("cvt.rna.tf32.f32 %0, %1;" : "=r"(r) : "f"(v));
    return __uint_as_float(r);
}
__device__ __forceinline__ float2 tfsplit(float v) {
    const float h = tf32_(v);
    return make_float2(h, tf32_(v - h));
}
__device__ __forceinline__ void mma8(float d[4], float a0, float a1, float a2, float a3,
                                     float b0, float b1) {
    asm("mma.sync.aligned.m16n8k8.row.col.f32.tf32.tf32.f32 "
        "{%0,%1,%2,%3}, {%4,%5,%6,%7}, {%8,%9}, {%0,%1,%2,%3};"
        : "+f"(d[0]), "+f"(d[1]), "+f"(d[2]), "+f"(d[3])
        : "r"(__float_as_uint(a0)), "r"(__float_as_uint(a1)),
          "r"(__float_as_uint(a2)), "r"(__float_as_uint(a3)),
          "r"(__float_as_uint(b0)), "r"(__float_as_uint(b1)));
}
__device__ __forceinline__ void mma3(float d[4], const float2 F[4], float2 b0, float2 b1) {
    mma8(d, F[0].x, F[1].x, F[2].x, F[3].x, b0.x, b1.x);
    mma8(d, F[0].x, F[1].x, F[2].x, F[3].x, b0.y, b1.y);
    mma8(d, F[0].y, F[1].y, F[2].y, F[3].y, b0.x, b1.x);
}
__device__ __forceinline__ void ldfrag(float2 F[8], const float2* base, int st, int g, int col) {
    F[0] = base[g * st + col];            F[1] = base[(g + 8) * st + col];
    F[2] = base[g * st + col + 4];        F[3] = base[(g + 8) * st + col + 4];
    F[4] = base[(g + 16) * st + col];     F[5] = base[(g + 24) * st + col];
    F[6] = base[(g + 16) * st + col + 4]; F[7] = base[(g + 24) * st + col + 4];
}
__device__ __forceinline__ float rcp_(float x) {
    float r; asm("rcp.approx.f32 %0, %1;" : "=f"(r) : "f"(x)); return r;
}
__device__ __forceinline__ void rcp4(const float d[4], float inv[4]) {
    const float p1 = d[0] * d[1], p2 = p1 * d[2], p3 = p2 * d[3];
    const float q3 = rcp_(p3);
    inv[3] = q3 * p2;
    const float q2 = q3 * d[3];
    inv[2] = q2 * p1;
    const float q1 = q2 * d[2];
    inv[1] = q1 * d[0];
    inv[0] = q1 * d[1];
}
__device__ __forceinline__ float fsig(float x) {
    return __fdividef(1.0f, 1.0f + __expf(-x));
}
__device__ __forceinline__ float ftanh_(float x) {
    float e = __expf(2.0f * x);
    return 1.0f - __fdividef(2.0f, e + 1.0f);
}

__global__ void prep_kernel(const float* __restrict__ Wih, const float* __restrict__ Whh,
                            const float* __restrict__ Wl1, const float* __restrict__ Wl2)
{
    const int total = KP * NP + 104 * 104 + 104 * 64;
    for (int i = blockIdx.x * blockDim.x + threadIdx.x; i < total;
         i += gridDim.x * blockDim.x) {
        float v = 0.f;
        if (i < KP * NP) {
            const int k = i / NP, n = i % NP;
            if (n < 200) {
                if (k < XD) v = Wih[k * 300 + n];
                else if (k < 228) v = Whh[(k - XD) * 300 + n];
            } else if (n < 300) {
                if (k < XD) v = Wih[k * 300 + n];
            } else if (n >= 304 && n < 404) {
                if (k >= XD && k < 228) v = Whh[(k - XD) * 300 + (n - 104)];
            }
            g_WB[i] = tfsplit(v);
        } else if (i < KP * NP + 104 * 104) {
            const int e = i - KP * NP, k = e / 104, n = e % 104;
            if (k < 100 && n < 100) v = Wl1[k * 100 + n];
            g_W1[e] = tfsplit(v);
        } else {
            const int e = i - KP * NP - 104 * 104, k = e / 64, n = e % 64;
            if (k < 100) v = Wl2[k * 64 + n];
            g_W2[e] = tfsplit(v);
        }
    }
}

extern "C" __global__ void __launch_bounds__(NT, 1) gru_kernel(
    const float* __restrict__ x, const float* __restrict__ y, const void* __restrict__ ymask,
    const float* __restrict__ Wmu1, const float* __restrict__ bmu1,
    const float* __restrict__ Wmu2, const float* __restrict__ bmu2,
    const float* __restrict__ bih, const float* __restrict__ bhh,
    const float* __restrict__ bl1, const float* __restrict__ bl2,
    const float* __restrict__ Wc1, const float* __restrict__ bc1,
    const float* __restrict__ Wc2, const float* __restrict__ bc2,
    float* __restrict__ out, int has_cls)
{
    extern __shared__ float sm[];
    float2* Af  = (float2*)(sm + OFF_A);
    float2* O1f = (float2*)(sm + OFF_GX);
    const int tid  = threadIdx.x;
    const int lane = tid & 31;
    const int wid  = tid >> 5;        // 0..31
    const int g    = lane >> 2;
    const int cc   = lane & 3;
    const int b0   = (B_ * blockIdx.x) / NBK;
    const int nr   = (B_ * (blockIdx.x + 1)) / NBK - b0;   // 27 or 28
    const int j0   = lane * 4;

    // ---- stage biases; zero YP + A pad cols ----
    for (int i = tid; i < 300; i += NT) {
        sm[OFF_BIH + i] = (i < 200) ? bih[i] + bhh[i] : bih[i];
        sm[OFF_BHH + i] = bhh[i];
    }
    for (int i = tid; i < LAT; i += NT) sm[OFF_BL1 + i] = bl1[i];
    for (int i = tid; i < YD;  i += NT) sm[OFF_BL2 + i] = bl2[i];
    for (int i = tid; i < YD * 33; i += NT) sm[OFF_YP + i] = 0.f;
    if (tid < 128) Af[(tid >> 2) * AS2 + 228 + (tid & 3)] = make_float2(0.f, 0.f);

    // ---- mask dtype detection ----
    const unsigned word = ((const unsigned*)ymask)[tid & 255];
    const int big = __syncthreads_or((word & 0xFEFEFEFEu) != 0u);
    const int odd = __syncthreads_or((word & 0xFFFFFF00u) != 0u);
    const int mode = big ? 2 : (odd ? 0 : 1);

    // ---- stage x fp32 into GX scratch [32][132] ----
    float* Xs = sm + OFF_GX;
    for (int i = tid; i < 32 * XD; i += NT) {
        const int r = i & 31, k = i >> 5;
        Xs[r * 132 + k] = (r < nr) ? __ldg(&x[(size_t)(b0 + r) * XD + k]) : 0.f;
    }
    __syncthreads();

    // ---- h0 encoder (FFMA, once): warp = row (32 warps = 32 rows) ----
    float* tmp = sm + OFF_GX + 4224;   // [100][36]
    if (lane < 25) {
        float a[4] = {0, 0, 0, 0};
        for (int k = 0; k < XD; k++) {
            const float xv = Xs[wid * 132 + k];
            const float4 w = __ldg((const float4*)&Wmu1[k * LAT + j0]);
            a[0] = fmaf(xv, w.x, a[0]); a[1] = fmaf(xv, w.y, a[1]);
            a[2] = fmaf(xv, w.z, a[2]); a[3] = fmaf(xv, w.w, a[3]);
        }
        const float4 bb = __ldg((const float4*)&bmu1[j0]);
        tmp[(j0 + 0) * 36 + wid] = ftanh_(a[0] + bb.x);
        tmp[(j0 + 1) * 36 + wid] = ftanh_(a[1] + bb.y);
        tmp[(j0 + 2) * 36 + wid] = ftanh_(a[2] + bb.z);
        tmp[(j0 + 3) * 36 + wid] = ftanh_(a[3] + bb.w);
    }
    __syncthreads();
    if (lane < 25) {
        float a[4] = {0, 0, 0, 0};
        for (int k = 0; k < LAT; k++) {
            const float tv = tmp[k * 36 + wid];
            const float4 w = __ldg((const float4*)&Wmu2[k * LAT + j0]);
            a[0] = fmaf(tv, w.x, a[0]); a[1] = fmaf(tv, w.y, a[1]);
            a[2] = fmaf(tv, w.z, a[2]); a[3] = fmaf(tv, w.w, a[3]);
        }
        const float4 bb = __ldg((const float4*)&bmu2[j0]);
        const float hv[4] = {a[0] + bb.x, a[1] + bb.y, a[2] + bb.z, a[3] + bb.w};
#pragma unroll
        for (int i = 0; i < 4; i++) {
            sm[OFF_H + (j0 + i) * 36 + wid] = hv[i];
            Af[wid * AS2 + 128 + j0 + i] = tfsplit(hv[i]);
        }
    }

    // ---- y/mask preload (2048 = 32r x 64d, 2/thread) ----
    float yv[2], mfv[2];
    auto preload = [&](int t) {
#pragma unroll
        for (int i = 0; i < 2; i++) {
            const int e = tid + NT * i;
            const int r = e & 31, d = e >> 5;
            if (r < nr) {
                const size_t off = (size_t)(b0 + r) * (YD * T_) + (size_t)d * T_ + t;
                yv[i] = __ldg(&y[off]);
                float m;
                if (mode == 0)      m = (((const unsigned char*)ymask)[off] != 0) ? 1.f : 0.f;
                else if (mode == 1) m = (((const int*)ymask)[off] != 0) ? 1.f : 0.f;
                else                m = (((const float*)ymask)[off] != 0.f) ? 1.f : 0.f;
                mfv[i] = m;
            } else { yv[i] = 0.f; mfv[i] = 0.f; }
        }
    };
    preload(0);
    __syncthreads();

    // ================= main recurrence (5 barriers/step) =================
    for (int t = 0; t < T_; ++t) {
        // -- teacher forcing -> A cols 0..127 --
#pragma unroll
        for (int i = 0; i < 2; i++) {
            const int e = tid + NT * i;
            const int r = e & 31, d = e >> 5;
            const float m  = mfv[i];
            const float yp = sm[OFF_YP + d * 33 + r];
            const float yin = (m != 0.f) ? yv[i] : yp;
            Af[r * AS2 + 2 * d]     = tfsplit(yin);
            Af[r * AS2 + 2 * d + 1] = make_float2(m, 0.f);
        }
        if (t + 1 < T_) preload(t + 1);
        __syncthreads();

        // -- P1 (tensor): tile-outer, contiguous kt ranges, balanced TSET --
#pragma unroll
        for (int q = 0; q < 3; q++) {
            const int tl = TSET[wid][q];
            if (tl < 0) break;
            const int n0t = tl * 8;
            const int k0 = (n0t >= 304) ? 16 : 0;
            const int k1 = (n0t >= 200 && n0t < 304) ? 16 : NKT;
            float D[8];
#pragma unroll
            for (int i = 0; i < 8; i++) D[i] = 0.f;
            for (int kt = k0; kt < k1; kt++) {
                const int kk = kt * 8;
                float2 F[8];
                ldfrag(F, Af, AS2, g, kk + cc);
                const float2 b0v = __ldg(&g_WB[(kk + cc) * NP + n0t + g]);
                const float2 b1v = __ldg(&g_WB[(kk + cc + 4) * NP + n0t + g]);
                mma3(&D[0], F, b0v, b1v);
                mma3(&D[4], F + 4, b0v, b1v);
            }
#pragma unroll
            for (int i = 0; i < 8; i += 2) {
                const int row = g + (i >> 2) * 16 + ((i >> 1) & 1) * 8;
                *(float2*)&sm[OFF_GX + row * GST + n0t + 2 * cc] =
                    make_float2(D[i], D[i + 1]);
            }
        }
        __syncthreads();

        // -- gates (batched RCP): 800 items, 1/thread --
        if (tid < 800) {
            const int j  = tid % 100;
            const int r0 = (tid / 100) << 2;
            float gr[4], gz[4], gxv[4], gh[4];
#pragma unroll
            for (int i = 0; i < 4; i++) {
                const float* GX = sm + OFF_GX + (r0 + i) * GST;
                gr[i]  = GX[j]       + sm[OFF_BIH + j];
                gz[i]  = GX[100 + j] + sm[OFF_BIH + 100 + j];
                gxv[i] = GX[200 + j] + sm[OFF_BIH + 200 + j];
                gh[i]  = GX[304 + j] + sm[OFF_BHH + 200 + j];
            }
            float dr[4], dz[4], rg[4], zg[4];
#pragma unroll
            for (int i = 0; i < 4; i++) {
                dr[i] = 1.f + __expf(-fminf(fmaxf(gr[i], -15.f), 15.f));
                dz[i] = 1.f + __expf(-fminf(fmaxf(gz[i], -15.f), 15.f));
            }
            rcp4(dr, rg);
            rcp4(dz, zg);
            float dn[4], iv[4];
#pragma unroll
            for (int i = 0; i < 4; i++) {
                float u = gxv[i] + rg[i] * gh[i];
                u = fminf(fmaxf(u, -10.f), 10.f);
                dn[i] = __expf(2.f * u) + 1.f;
            }
            rcp4(dn, iv);
#pragma unroll
            for (int i = 0; i < 4; i++) {
                const float n  = 1.f - 2.f * iv[i];
                const float ho = sm[OFF_H + j * 36 + r0 + i];
                const float hn = (1.f - zg[i]) * n + zg[i] * ho;
                sm[OFF_H + j * 36 + r0 + i] = hn;
                Af[(r0 + i) * AS2 + 128 + j] = tfsplit(hn);
            }
        }
        __syncthreads();

        // -- G3 (tensor): o1 = tanh(h @ Wl1 + bl1) -> O1f --
        if (wid < 13) {
            const int n0 = wid * 8;
            float D[8];
#pragma unroll
            for (int i = 0; i < 8; i++) D[i] = 0.f;
            for (int kt = 0; kt < 13; kt++) {
                const int kk = kt * 8;
                float2 F[8];
                ldfrag(F, Af, AS2, g, 128 + kk + cc);
                const float2 b0v = __ldg(&g_W1[(kk + cc) * 104 + n0 + g]);
                const float2 b1v = __ldg(&g_W1[(kk + cc + 4) * 104 + n0 + g]);
                mma3(&D[0], F, b0v, b1v);
                mma3(&D[4], F + 4, b0v, b1v);
            }
            float dv[8], iv[8];
#pragma unroll
            for (int i = 0; i < 8; i++) {
                const int col = n0 + 2 * cc + (i & 1);
                const float bb = (col < 100) ? sm[OFF_BL1 + col] : 0.f;
                const float u = fminf(fmaxf(D[i] + bb, -10.f), 10.f);
                dv[i] = __expf(2.f * u) + 1.f;
            }
            rcp4(dv, iv);
            rcp4(dv + 4, iv + 4);
#pragma unroll
            for (int i = 0; i < 8; i++) {
                const int row = g + (i >> 2) * 16 + ((i >> 1) & 1) * 8;
                const int col = n0 + 2 * cc + (i & 1);
                O1f[row * O1S + col] = tfsplit(1.f - 2.f * iv[i]);
            }
        }
        __syncthreads();

        // -- G4 (tensor): out_t = o1 @ Wl2 + bl2; writes out + YP --
        if (wid < 8) {
            const int n0 = wid * 8;
            float D[8];
#pragma unroll
            for (int i = 0; i < 8; i++) D[i] = 0.f;
            for (int kt = 0; kt < 13; kt++) {
                const int kk = kt * 8;
                float2 F[8];
                ldfrag(F, O1f, O1S, g, kk + cc);
                const float2 b0v = __ldg(&g_W2[(kk + cc) * 64 + n0 + g]);
                const float2 b1v = __ldg(&g_W2[(kk + cc + 4) * 64 + n0 + g]);
                mma3(&D[0], F, b0v, b1v);
                mma3(&D[4], F + 4, b0v, b1v);
            }
#pragma unroll
            for (int i = 0; i < 8; i++) {
                const int row = g + (i >> 2) * 16 + ((i >> 1) & 1) * 8;
                const int col = n0 + 2 * cc + (i & 1);
                const float v = D[i] + sm[OFF_BL2 + col];
                if (row < nr)
                    out[(size_t)(b0 + row) * (YD * T_) + (size_t)col * T_ + t] = v;
                sm[OFF_YP + col * 33 + row] = v;
            }
        }
        __syncthreads();
    }

    // ---- classifier ----
    if (has_cls) {
        float* scr = sm + OFF_GX;
        for (int idx = tid; idx < 32 * CH; idx += NT) {
            const int r = idx & 31, c = idx >> 5;
            float acc = __ldg(&bc1[c]);
            for (int k = 0; k < LAT; k++)
                acc = fmaf(sm[OFF_H + k * 36 + r], __ldg(&Wc1[k * CH + c]), acc);
            scr[c * 36 + r] = fmaxf(acc, 0.f);
        }
        __syncthreads();
        if (tid < nr) {
            float acc = __ldg(&bc2[0]);
            for (int c = 0; c < CH; c++)
                acc = fmaf(scr[c * 36 + tid], __ldg(&Wc2[c]), acc);
            out[(size_t)B_ * YD * T_ + b0 + tid] = fsig(acc);
        }
    }
}

extern "C" void kernel_launch(void* const* d_in, const int* in_sizes, int n_in,
                              void* d_out, int out_size)
{
    cudaFuncSetAttribute(gru_kernel, cudaFuncAttributeMaxDynamicSharedMemorySize,
                         SMEM_FLOATS * (int)sizeof(float));
    prep_kernel<<<128, 256>>>((const float*)d_in[11], (const float*)d_in[13],
                              (const float*)d_in[15], (const float*)d_in[17]);
    const int has_cls = (out_size > B_ * YD * T_) ? 1 : 0;
    gru_kernel<<<NBK, NT, SMEM_FLOATS * sizeof(float)>>>(
        (const float*)d_in[0],   // x
        (const float*)d_in[1],   // y
        d_in[2],                 // y_mask (dtype auto-detected)
        (const float*)d_in[3],  (const float*)d_in[4],   // Wmu1, bmu1
        (const float*)d_in[5],  (const float*)d_in[6],   // Wmu2, bmu2
        (const float*)d_in[12], (const float*)d_in[14],  // bih, bhh
        (const float*)d_in[16], (const float*)d_in[18],  // bl1, bl2
        (const float*)d_in[19], (const float*)d_in[20],  // Wc1, bc1
        (const float*)d_in[21], (const float*)d_in[22],  // Wc2, bc2
        (float*)d_out, has_cls);
}